// round 1
// baseline (speedup 1.0000x reference)
#include <cuda_runtime.h>
#include <cstdint>

typedef unsigned long long u64;

#define B_   16
#define T_   1024
#define E_   128
#define H_   256
#define G4_  1024
#define NC_  8000

// -------- scratch (static device arrays: no runtime allocation) ----------
__device__ float g_xproj[(size_t)T_ * B_ * G4_];   // [t][b][g]  64 MB
__device__ float g_hs[(size_t)B_ * T_ * H_];       // [b][t][h]  16 MB
__device__ int   g_counters[B_];
__device__ int   g_xlong;

// -------- packed f32x2 helpers ----------
__device__ __forceinline__ void ffma2(u64 &d, u64 a, u64 b) {
    asm("fma.rn.f32x2 %0, %1, %2, %0;" : "+l"(d) : "l"(a), "l"(b));
}
__device__ __forceinline__ u64 fpack(float x, float y) {
    u64 r; asm("mov.b64 %0, {%1, %2};" : "=l"(r) : "f"(x), "f"(y)); return r;
}
__device__ __forceinline__ float2 funpack(u64 v) {
    float2 r; asm("mov.b64 {%0, %1}, %2;" : "=f"(r.x), "=f"(r.y) : "l"(v)); return r;
}
__device__ __forceinline__ float sigm(float x) { return 1.0f / (1.0f + expf(-x)); }

// ===========================================================================
// K0: detect x dtype (int64 vs int32) + zero the group counters
// ===========================================================================
__global__ void k_init(const void *xraw) {
    if (threadIdx.x == 0) {
        const unsigned int *xi = (const unsigned int *)xraw;
        int i64 = 1;
        for (int i = 0; i < 64; i++)
            if (xi[2 * i + 1] != 0u) { i64 = 0; break; }
        g_xlong = i64;
    }
    if (threadIdx.x < B_) g_counters[threadIdx.x] = 0;
}

// ===========================================================================
// K1: embedding gather + input projection
//   x_proj[t][b][g] = sum_e inp[t,b,e] * W_ih[g,e] + b_ih[g] + b_hh[g]
// one block per t; 256 threads; each thread owns gates {tid, tid+256, tid+512, tid+768}
// ===========================================================================
#define IST 18   // inp_s stride (bank pad, keeps float2 alignment)

__global__ void __launch_bounds__(256) k_embed_proj(
    const void *xraw, const float *embx, const float *embl,
    const float *Wih, const float *bih, const float *bhh)
{
    const int t = blockIdx.x;
    __shared__ float inp_s[256 * IST];
    __shared__ int xs[B_], ls[B_];
    const int tid = threadIdx.x;

    if (tid < 32) {
        int b = tid >> 1, j = tid & 1;
        long long e = (long long)b * (T_ * 2) + t * 2 + j;
        int v;
        if (g_xlong) v = (int)((const long long *)xraw)[e];
        else         v = ((const int *)xraw)[e];
        if (j == 0) xs[b] = v; else ls[b] = v;
    }
    __syncthreads();

    for (int idx = tid; idx < B_ * 256; idx += 256) {
        int b = idx >> 8, k = idx & 255;
        float v = (k < E_) ? embx[xs[b] * E_ + k] : embl[ls[b] * E_ + (k - E_)];
        inp_s[k * IST + b] = v;
    }
    __syncthreads();

    int row[4];
    u64 acc[4][8];
#pragma unroll
    for (int j = 0; j < 4; j++) {
        row[j] = j * 256 + tid;
#pragma unroll
        for (int p = 0; p < 8; p++) acc[j][p] = 0ULL;
    }

    for (int kc = 0; kc < 64; kc++) {
        float4 w4[4];
#pragma unroll
        for (int j = 0; j < 4; j++)
            w4[j] = *(const float4 *)(Wih + (size_t)row[j] * 256 + kc * 4);
#pragma unroll
        for (int kk = 0; kk < 4; kk++) {
            const float *ip = inp_s + (kc * 4 + kk) * IST;
            u64 wd[4];
            {
                float w0 = (&w4[0].x)[kk], w1 = (&w4[1].x)[kk];
                float w2 = (&w4[2].x)[kk], w3 = (&w4[3].x)[kk];
                wd[0] = fpack(w0, w0); wd[1] = fpack(w1, w1);
                wd[2] = fpack(w2, w2); wd[3] = fpack(w3, w3);
            }
#pragma unroll
            for (int p = 0; p < 8; p++) {
                u64 h2 = *(const u64 *)(ip + 2 * p);
                ffma2(acc[0][p], wd[0], h2);
                ffma2(acc[1][p], wd[1], h2);
                ffma2(acc[2][p], wd[2], h2);
                ffma2(acc[3][p], wd[3], h2);
            }
        }
    }

#pragma unroll
    for (int j = 0; j < 4; j++) {
        float bias = bih[row[j]] + bhh[row[j]];
        float *base = g_xproj + (size_t)t * (B_ * G4_);
#pragma unroll
        for (int p = 0; p < 8; p++) {
            float2 v = funpack(acc[j][p]);
            base[(2 * p)     * G4_ + row[j]] = v.x + bias;
            base[(2 * p + 1) * G4_ + row[j]] = v.y + bias;
        }
    }
}

// ===========================================================================
// K2: LSTM recurrence. 16 batch-groups x 8 CTAs (persistent, all resident).
// CTA (b,grp): owns hidden [grp*32, grp*32+32) of each of the 4 gates.
// W_hh slice held in registers (64 f32x2 regs / thread, 512 threads).
// h(t-1) read from g_hs[b][t-1] (unique address per step -> no L1 staleness).
// Group sync: STG h + threadfence + atomicAdd; consumer acquire-poll + fence.
// ===========================================================================
#define HS_STRIDE 66   // padded per-quarter h stride (bank-conflict-free)

__global__ void __launch_bounds__(512, 1) k_lstm(const float *Whh)
{
    const int b   = blockIdx.x >> 3;
    const int grp = blockIdx.x & 7;
    const int tid = threadIdx.x;
    const int r = tid >> 2;        // 0..127 : local row = gate*32 + lh
    const int q = tid & 3;         // K quarter (64 each)
    const int gate = r >> 5, lh = r & 31;
    const int h0 = grp * 32;
    const int row_g = gate * H_ + h0 + lh;

    __shared__ float h_s[4 * HS_STRIDE];
    __shared__ float gates_s[128];
    __shared__ float c_s[32];

    // load weights to registers
    u64 w2[32];
    {
        const float *wp = Whh + (size_t)row_g * H_ + q * 64;
#pragma unroll
        for (int j = 0; j < 32; j++) w2[j] = *(const u64 *)(wp + 2 * j);
    }

    for (int t = 0; t < T_; t++) {
        if (t > 0) {
            if (tid == 0) {
                const int target = 256 * t;
                while (*(volatile int *)(g_counters + b) < target) { }
                __threadfence();
            }
            __syncthreads();
            if (tid < 128) {
                int k = tid * 2;
                u64 v = *(const u64 *)(g_hs + ((size_t)b * T_ + (t - 1)) * H_ + k);
                *(u64 *)(h_s + (k >> 6) * HS_STRIDE + (k & 63)) = v;
            }
        } else {
            if (tid < 2 * HS_STRIDE) ((u64 *)h_s)[tid] = 0ULL;
        }

        float xp = 0.0f;
        if (q == 0) xp = g_xproj[(size_t)t * (B_ * G4_) + b * G4_ + row_g];
        __syncthreads();

        u64 a0 = 0, a1 = 0, a2 = 0, a3 = 0;
        const float *hq = h_s + q * HS_STRIDE;
#pragma unroll
        for (int j = 0; j < 32; j += 4) {
            ffma2(a0, w2[j + 0], *(const u64 *)(hq + 2 * j + 0));
            ffma2(a1, w2[j + 1], *(const u64 *)(hq + 2 * j + 2));
            ffma2(a2, w2[j + 2], *(const u64 *)(hq + 2 * j + 4));
            ffma2(a3, w2[j + 3], *(const u64 *)(hq + 2 * j + 6));
        }
        float2 s0 = funpack(a0), s1 = funpack(a1), s2 = funpack(a2), s3 = funpack(a3);
        float sum = ((s0.x + s0.y) + (s1.x + s1.y)) + ((s2.x + s2.y) + (s3.x + s3.y));
        sum += __shfl_xor_sync(0xffffffffu, sum, 1);
        sum += __shfl_xor_sync(0xffffffffu, sum, 2);
        if (q == 0) gates_s[r] = sum + xp;
        __syncthreads();

        if (tid < 32) {
            float iv = sigm(gates_s[tid]);
            float fv = sigm(gates_s[32 + tid]);
            float gv = tanhf(gates_s[64 + tid]);
            float ov = sigm(gates_s[96 + tid]);
            float c  = (t == 0) ? 0.0f : c_s[tid];
            float cn = fv * c + iv * gv;
            c_s[tid] = cn;
            float hn = ov * tanhf(cn);
            g_hs[((size_t)b * T_ + t) * H_ + h0 + tid] = hn;
            __threadfence();
            atomicAdd(g_counters + b, 1);
        }
    }
}

// ===========================================================================
// K3: final FC GEMM  out[m][c] = hs[m][:] . fc_w[c][:] + fc_b[c]
//   M = 16384 (b*1024+t), N = 8000, K = 256
// block tile 128m x 64n, 256 threads, 8m x 4n microtile (f32x2 over m-pairs)
// ===========================================================================
#define ASTR 130
#define BSTR 66

__global__ void __launch_bounds__(256) k_fc(const float *fcw, const float *fcb, float *out)
{
    const int bn = blockIdx.x * 64;
    const int bm = blockIdx.y * 128;
    __shared__ float As[32 * ASTR];
    __shared__ float Bs[32 * BSTR];
    const int tid = threadIdx.x;
    const int tx = tid & 15;     // n: 4 each
    const int ty = tid >> 4;     // m: 8 each

    u64 acc[4][4];
#pragma unroll
    for (int i = 0; i < 4; i++)
#pragma unroll
        for (int j = 0; j < 4; j++) acc[i][j] = 0ULL;

    for (int kc = 0; kc < 8; kc++) {
        __syncthreads();
#pragma unroll
        for (int i = 0; i < 4; i++) {
            int s = tid + 256 * i;
            int rowm = s >> 3, kq = s & 7;
            float4 v = *(const float4 *)(g_hs + (size_t)(bm + rowm) * 256 + kc * 32 + kq * 4);
            As[(kq * 4 + 0) * ASTR + rowm] = v.x;
            As[(kq * 4 + 1) * ASTR + rowm] = v.y;
            As[(kq * 4 + 2) * ASTR + rowm] = v.z;
            As[(kq * 4 + 3) * ASTR + rowm] = v.w;
        }
#pragma unroll
        for (int i = 0; i < 2; i++) {
            int s = tid + 256 * i;
            int rown = s >> 3, kq = s & 7;
            float4 v = *(const float4 *)(fcw + (size_t)(bn + rown) * 256 + kc * 32 + kq * 4);
            Bs[(kq * 4 + 0) * BSTR + rown] = v.x;
            Bs[(kq * 4 + 1) * BSTR + rown] = v.y;
            Bs[(kq * 4 + 2) * BSTR + rown] = v.z;
            Bs[(kq * 4 + 3) * BSTR + rown] = v.w;
        }
        __syncthreads();

#pragma unroll
        for (int k = 0; k < 32; k++) {
            const float *ar = As + k * ASTR + ty * 8;
            const float *br = Bs + k * BSTR + tx * 4;
            u64 a2[4];
#pragma unroll
            for (int i = 0; i < 4; i++) a2[i] = *(const u64 *)(ar + 2 * i);
            float2 b01 = funpack(*(const u64 *)(br));
            float2 b23 = funpack(*(const u64 *)(br + 2));
            u64 bd0 = fpack(b01.x, b01.x), bd1 = fpack(b01.y, b01.y);
            u64 bd2 = fpack(b23.x, b23.x), bd3 = fpack(b23.y, b23.y);
#pragma unroll
            for (int i = 0; i < 4; i++) {
                ffma2(acc[i][0], a2[i], bd0);
                ffma2(acc[i][1], a2[i], bd1);
                ffma2(acc[i][2], a2[i], bd2);
                ffma2(acc[i][3], a2[i], bd3);
            }
        }
    }

    float fb0 = fcb[bn + tx * 4 + 0], fb1 = fcb[bn + tx * 4 + 1];
    float fb2 = fcb[bn + tx * 4 + 2], fb3 = fcb[bn + tx * 4 + 3];
#pragma unroll
    for (int i = 0; i < 4; i++) {
        float2 c0 = funpack(acc[i][0]), c1 = funpack(acc[i][1]);
        float2 c2 = funpack(acc[i][2]), c3 = funpack(acc[i][3]);
        int m = bm + ty * 8 + 2 * i;
        float4 o0 = make_float4(c0.x + fb0, c1.x + fb1, c2.x + fb2, c3.x + fb3);
        float4 o1 = make_float4(c0.y + fb0, c1.y + fb1, c2.y + fb2, c3.y + fb3);
        *(float4 *)(out + (size_t)m * NC_ + bn + tx * 4)       = o0;
        *(float4 *)(out + (size_t)(m + 1) * NC_ + bn + tx * 4) = o1;
    }
}

// ===========================================================================
extern "C" void kernel_launch(void *const *d_in, const int *in_sizes, int n_in,
                              void *d_out, int out_size)
{
    (void)in_sizes; (void)n_in; (void)out_size;
    const void  *x    = d_in[0];
    const float *embx = (const float *)d_in[1];
    const float *embl = (const float *)d_in[2];
    const float *Wih  = (const float *)d_in[3];
    const float *Whh  = (const float *)d_in[4];
    const float *bih  = (const float *)d_in[5];
    const float *bhh  = (const float *)d_in[6];
    const float *fcw  = (const float *)d_in[7];
    const float *fcb  = (const float *)d_in[8];
    float *out = (float *)d_out;

    k_init<<<1, 32>>>(x);
    k_embed_proj<<<T_, 256>>>(x, embx, embl, Wih, bih, bhh);
    k_lstm<<<B_ * 8, 512>>>(Whh);
    k_fc<<<dim3(NC_ / 64, (B_ * T_) / 128), 256>>>(fcw, fcb, out);
}